// round 14
// baseline (speedup 1.0000x reference)
#include <cuda_runtime.h>
#include <cuda_fp16.h>
#include <math.h>
#include <stdint.h>

#define B_ 8
#define S_ 2048
#define D_ 1024
#define NROWS (B_ * S_)
#define BKH 32                        // k-halves per chunk (64B per row)
#define NSTAGE 5
#define STA 40                        // halves per SMEM row (80B = 64B + 16B pad)
#define TILE_BYTES (128 * 80)         // 10240 B per operand tile
#define SM_BYTES (NSTAGE * 2 * TILE_BYTES)   // 102400 B dynamic smem
#define NTHR 128                      // 4 warps, 2x2 grid of 64x64 warp tiles
#define NTRI 136                      // 16*17/2 lower-triangular 128-blocks

// Scratch (device globals: allowed; no runtime allocation)
__device__ __half g_xq[(size_t)NROWS * D_];   // fp16 copy of query
__device__ __half g_xk[(size_t)NROWS * D_];   // fp16 copy of key
__device__ __half g_xv[(size_t)NROWS * D_];   // fp16 copy of value
__device__ __half g_q[(size_t)NROWS * D_];    // q proj [row][d]
__device__ __half g_k[(size_t)NROWS * D_];    // k proj [row][d]
__device__ __half g_v[(size_t)NROWS * D_];    // v proj TRANSPOSED [b][d][s]
__device__ __half g_p[(size_t)B_ * S_ * S_];  // scores -> probs [b][sq][sk]
__device__ __half g_wt[3 * (size_t)D_ * D_];  // W^T fp16 [which][n][k]

// ---------------------------------------------------------------------------
// PTX helpers (base ISA: cp.async / ldmatrix / mma.sync — no tcgen05)
// ---------------------------------------------------------------------------
__device__ __forceinline__ uint32_t smem_u32(const void* p) {
    uint32_t a;
    asm("{ .reg .u64 t; cvta.to.shared.u64 t, %1; cvt.u32.u64 %0, t; }"
        : "=r"(a) : "l"(p));
    return a;
}

#define CP16(dst, src)                                                        \
    asm volatile("cp.async.cg.shared.global [%0], [%1], 16;"                  \
                 :: "r"(dst), "l"(src))
#define CP_COMMIT() asm volatile("cp.async.commit_group;" ::: "memory")
#define CP_WAIT3()  asm volatile("cp.async.wait_group 3;" ::: "memory")

#define LDMX4(r0, r1, r2, r3, addr)                                           \
    asm volatile("ldmatrix.sync.aligned.m8n8.x4.shared.b16 {%0,%1,%2,%3}, [%4];" \
                 : "=r"(r0), "=r"(r1), "=r"(r2), "=r"(r3) : "r"(addr))

#define MMA_F16(c, a, b)                                                      \
    asm volatile(                                                             \
        "mma.sync.aligned.m16n8k16.row.col.f32.f16.f16.f32 "                  \
        "{%0,%1,%2,%3}, {%4,%5,%6,%7}, {%8,%9}, {%0,%1,%2,%3};"               \
        : "+f"((c)[0]), "+f"((c)[1]), "+f"((c)[2]), "+f"((c)[3])              \
        : "r"((a)[0]), "r"((a)[1]), "r"((a)[2]), "r"((a)[3]),                 \
          "r"((b)[0]), "r"((b)[1]))

#define ZERO_ACC(acc)                                                         \
    _Pragma("unroll") for (int i = 0; i < 4; i++)                             \
    _Pragma("unroll") for (int j = 0; j < 8; j++)                             \
    _Pragma("unroll") for (int k = 0; k < 4; k++) (acc)[i][j][k] = 0.f

// ---------------------------------------------------------------------------
// cp.async one chunk: A tile 128x32h + B tile 128x32h (both [row][k] fp16).
// ---------------------------------------------------------------------------
__device__ __forceinline__ void issue_tile(uint32_t smA, const __half* Ag, size_t lda,
                                           uint32_t smB, const __half* Bg, size_t ldb,
                                           int j, int tid) {
#pragma unroll
    for (int w = 0; w < 4; w++) {
        const int lin = tid + (w << 7);          // 0..511
        const int r = lin >> 2, q = lin & 3;
        CP16(smA + r * 80 + (q << 4), Ag + (size_t)r * lda + j * BKH + (q << 3));
        CP16(smB + r * 80 + (q << 4), Bg + (size_t)r * ldb + j * BKH + (q << 3));
    }
}

// ---------------------------------------------------------------------------
// LDSM one k16 step's fragments for a 64x64 warp tile.
// ---------------------------------------------------------------------------
__device__ __forceinline__ void ldsm_frags(uint32_t smA, uint32_t smB, int k16,
                                           int wm, int wn, int lane,
                                           uint32_t af[4][4], uint32_t bf[8][2]) {
    const int a_row = lane & 15;
    const int a_k8  = ((lane >> 4) & 1) << 3;
    const int b_row = (lane & 7) + (((lane >> 4) & 1) << 3);
    const int b_k8  = ((lane >> 3) & 1) << 3;
#pragma unroll
    for (int im = 0; im < 4; im++) {
        uint32_t addr = smA +
            (uint32_t)(((wm + (im << 4) + a_row) * STA + k16 + a_k8) << 1);
        LDMX4(af[im][0], af[im][1], af[im][2], af[im][3], addr);
    }
#pragma unroll
    for (int ip = 0; ip < 4; ip++) {
        uint32_t addr = smB +
            (uint32_t)(((wn + (ip << 4) + b_row) * STA + k16 + b_k8) << 1);
        LDMX4(bf[2 * ip][0], bf[2 * ip][1], bf[2 * ip + 1][0], bf[2 * ip + 1][1], addr);
    }
}

__device__ __forceinline__ void mma_all(float acc[4][8][4],
                                        uint32_t af[4][4], uint32_t bf[8][2]) {
#pragma unroll
    for (int im = 0; im < 4; im++)
#pragma unroll
        for (int in = 0; in < 8; in++) MMA_F16(acc[im][in], af[im], bf[in]);
}

// ---------------------------------------------------------------------------
// CUTLASS-style 5-stage mainloop, chunk K=32h (2 k16 steps), frag ping-pong.
// (R8/R10 schedule — verified best of family; do not touch.)
// ---------------------------------------------------------------------------
__device__ __forceinline__ void gemm_cp(const __half* Ag, size_t lda,
                                        const __half* Bg, size_t ldb, int KT,
                                        float acc[4][8][4]) {
    extern __shared__ __half smh[];
    const int tid = threadIdx.x, lane = tid & 31, warp = tid >> 5;
    const int wm = (warp >> 1) << 6, wn = (warp & 1) << 6;
    const uint32_t smb = smem_u32(smh);

#pragma unroll
    for (int s = 0; s < 4; s++) {
        if (s < KT)
            issue_tile(smb + s * 2 * TILE_BYTES, Ag, lda,
                       smb + s * 2 * TILE_BYTES + TILE_BYTES, Bg, ldb, s, tid);
        CP_COMMIT();
    }
    CP_WAIT3();
    __syncthreads();

    uint32_t af[2][4][4], bf[2][8][2];
    ldsm_frags(smb, smb + TILE_BYTES, 0, wm, wn, lane, af[0], bf[0]);

    for (int j = 0; j < KT; ++j) {
        const uint32_t sA = smb + (j % NSTAGE) * 2 * TILE_BYTES;
        ldsm_frags(sA, sA + TILE_BYTES, 16, wm, wn, lane, af[1], bf[1]);

        const int jn = j + 4;
        if (jn < KT) {
            const uint32_t sN = smb + (jn % NSTAGE) * 2 * TILE_BYTES;
            issue_tile(sN, Ag, lda, sN + TILE_BYTES, Bg, ldb, jn, tid);
        }
        CP_COMMIT();

        mma_all(acc, af[0], bf[0]);            // step0 MMAs

        CP_WAIT3();
        __syncthreads();

        if (j + 1 < KT) {
            const uint32_t sB = smb + ((j + 1) % NSTAGE) * 2 * TILE_BYTES;
            ldsm_frags(sB, sB + TILE_BYTES, 0, wm, wn, lane, af[0], bf[0]);
        }
        mma_all(acc, af[1], bf[1]);            // step1 MMAs (frags pre-loaded)
    }
}

// ---------------------------------------------------------------------------
// Epilogues
// ---------------------------------------------------------------------------
__device__ __forceinline__ void epilogue_h(float acc[4][8][4], __half* out, size_t ld,
                                           const float* bias, float scale) {
    const int lane = threadIdx.x & 31, warp = threadIdx.x >> 5;
    const int g = lane >> 2, t = lane & 3;
    const int wm = (warp >> 1) << 6, wn = (warp & 1) << 6;
#pragma unroll
    for (int im = 0; im < 4; im++) {
#pragma unroll
        for (int in = 0; in < 8; in++) {
            const int r0 = wm + (im << 4) + g;
            const int c = wn + (in << 3) + (t << 1);
            const float b0 = bias ? bias[c] : 0.f;
            const float b1 = bias ? bias[c + 1] : 0.f;
            *(__half2*)(out + (size_t)r0 * ld + c) =
                __floats2half2_rn(acc[im][in][0] * scale + b0,
                                  acc[im][in][1] * scale + b1);
            *(__half2*)(out + (size_t)(r0 + 8) * ld + c) =
                __floats2half2_rn(acc[im][in][2] * scale + b0,
                                  acc[im][in][3] * scale + b1);
        }
    }
}

__device__ __forceinline__ void epilogue_f(float acc[4][8][4], float* out, size_t ld) {
    const int lane = threadIdx.x & 31, warp = threadIdx.x >> 5;
    const int g = lane >> 2, t = lane & 3;
    const int wm = (warp >> 1) << 6, wn = (warp & 1) << 6;
#pragma unroll
    for (int im = 0; im < 4; im++) {
#pragma unroll
        for (int in = 0; in < 8; in++) {
            const int r0 = wm + (im << 4) + g;
            const int c = wn + (in << 3) + (t << 1);
            *(float2*)(out + (size_t)r0 * ld + c) =
                make_float2(acc[im][in][0], acc[im][in][1]);
            *(float2*)(out + (size_t)(r0 + 8) * ld + c) =
                make_float2(acc[im][in][2], acc[im][in][3]);
        }
    }
}

// Transposed store for V: vt is [D][S] for this batch (fp16).
__device__ __forceinline__ void epilogue_vt(float acc[4][8][4], __half* vt,
                                            int mloc, int n0, const float* bias) {
    const int lane = threadIdx.x & 31, warp = threadIdx.x >> 5;
    const int g = lane >> 2, t = lane & 3;
    const int wm = (warp >> 1) << 6, wn = (warp & 1) << 6;
#pragma unroll
    for (int im = 0; im < 4; im++) {
#pragma unroll
        for (int in = 0; in < 8; in++) {
            const int r = mloc + wm + (im << 4) + g;
            const int c = n0 + wn + (in << 3) + (t << 1);
            const float b0 = bias[c], b1 = bias[c + 1];
            vt[(size_t)c * S_ + r]           = __float2half_rn(acc[im][in][0] + b0);
            vt[(size_t)(c + 1) * S_ + r]     = __float2half_rn(acc[im][in][1] + b1);
            vt[(size_t)c * S_ + r + 8]       = __float2half_rn(acc[im][in][2] + b0);
            vt[(size_t)(c + 1) * S_ + r + 8] = __float2half_rn(acc[im][in][3] + b1);
        }
    }
}

// ---------------------------------------------------------------------------
// Kernel 0a: fp32 -> fp16 convert of raw query/key/value
// ---------------------------------------------------------------------------
__global__ __launch_bounds__(256) void cvt_inputs_kernel(
    const float* __restrict__ q, const float* __restrict__ k,
    const float* __restrict__ v) {
    const int z = blockIdx.z;
    const float* src = (z == 0) ? q : (z == 1) ? k : v;
    __half* dst = (z == 0) ? g_xq : (z == 1) ? g_xk : g_xv;
    const size_t i = ((size_t)blockIdx.x * 256 + threadIdx.x) * 4;
    float4 f = *(const float4*)(src + i);
    __half2* d2 = (__half2*)(dst + i);
    d2[0] = __floats2half2_rn(f.x, f.y);
    d2[1] = __floats2half2_rn(f.z, f.w);
}

// ---------------------------------------------------------------------------
// Kernel 0b: W ([k][n] fp32) -> g_wt ([n][k] fp16). No input deps besides W.
// ---------------------------------------------------------------------------
__global__ __launch_bounds__(256) void wt_kernel(const float* __restrict__ Wq,
                                                 const float* __restrict__ Wk,
                                                 const float* __restrict__ Wv) {
    const int z = blockIdx.z;
    const float* W = (z == 0) ? Wq : (z == 1) ? Wk : Wv;
    __half* WT = g_wt + (size_t)z * D_ * D_;
    __shared__ float t[32][33];
    const int tx = threadIdx.x & 31, ty = threadIdx.x >> 5;
    const int x0 = blockIdx.x << 5, y0 = blockIdx.y << 5;
#pragma unroll
    for (int i = 0; i < 4; i++)
        t[ty + i * 8][tx] = W[(size_t)(y0 + ty + i * 8) * D_ + x0 + tx];
    __syncthreads();
#pragma unroll
    for (int i = 0; i < 4; i++)
        WT[(size_t)(x0 + ty + i * 8) * D_ + y0 + tx] = __float2half_rn(t[tx][ty + i * 8]);
}

// ---------------------------------------------------------------------------
// Kernel 1: QKV projection  C = X @ W + b.  which = blockIdx.z + which_base.
// ---------------------------------------------------------------------------
__global__ __launch_bounds__(NTHR, 2) void qkv_mma_kernel(
    const float* __restrict__ bq, const float* __restrict__ bk,
    const float* __restrict__ bv, int which_base)
{
    const int which = blockIdx.z + which_base;
    const __half* A   = (which == 0) ? g_xq : (which == 1) ? g_xk : g_xv;
    const float* bias = (which == 0) ? bq   : (which == 1) ? bk   : bv;

    const int m0 = blockIdx.y << 7, n0 = blockIdx.x << 7;
    float acc[4][8][4];
    ZERO_ACC(acc);
    gemm_cp(A + (size_t)m0 * D_, D_,
            g_wt + (size_t)which * D_ * D_ + (size_t)n0 * D_, D_, D_ / BKH, acc);

    if (which == 2) {
        const int b = m0 >> 11;
        epilogue_vt(acc, g_v + (size_t)b * D_ * S_, m0 & (S_ - 1), n0, bias);
    } else {
        __half* C = (which == 0) ? g_q : g_k;
        epilogue_h(acc, C + (size_t)m0 * D_ + n0, D_, bias + n0, 1.0f);
    }
}

// ---------------------------------------------------------------------------
// Kernel 2: scores = (Q @ K^T)/32 — triangular-packed grid, no empty CTAs.
// ---------------------------------------------------------------------------
__global__ __launch_bounds__(NTHR, 2) void scores_mma_kernel()
{
    const int i = blockIdx.x;
    int bm = (int)((sqrtf(8.f * (float)i + 1.f) - 1.f) * 0.5f);
    if ((bm + 1) * (bm + 2) / 2 <= i) bm++;
    else if (bm * (bm + 1) / 2 > i) bm--;
    const int bn = i - bm * (bm + 1) / 2;
    const int b = blockIdx.y;
    const int m0 = bm << 7, n0 = bn << 7;

    float acc[4][8][4];
    ZERO_ACC(acc);
    gemm_cp(g_q + (size_t)b * S_ * D_ + (size_t)m0 * D_, D_,
            g_k + (size_t)b * S_ * D_ + (size_t)n0 * D_, D_, D_ / BKH, acc);
    epilogue_h(acc, g_p + (size_t)b * S_ * S_ + (size_t)m0 * S_ + n0, S_,
               nullptr, 0.03125f);
}

// ---------------------------------------------------------------------------
// Kernel 3: causal row softmax (vectorized), over rows [m_base, m_base+grid.x)
// ---------------------------------------------------------------------------
__global__ __launch_bounds__(256) void softmax_kernel(int m_base)
{
    const int m = m_base + blockIdx.x;
    const int b = blockIdx.y;
    __half* row = g_p + ((size_t)b * S_ + m) * S_;
    const int L = m + 1;
    const int Lpad = ((m >> 7) + 1) << 7;

    const int tid = threadIdx.x;
    const int lane = tid & 31, wid = tid >> 5;
    const int i0 = tid << 3;

    __shared__ float red[8];

    uint4 raw = *(const uint4*)(row + i0);
    const __half2* h2 = (const __half2*)&raw;
    float v[8];
#pragma unroll
    for (int k = 0; k < 4; k++) {
        float2 f = __half22float2(h2[k]);
        v[2 * k] = f.x;
        v[2 * k + 1] = f.y;
    }

    float mx = -INFINITY;
#pragma unroll
    for (int k = 0; k < 8; k++) {
        if (i0 + k < L) mx = fmaxf(mx, v[k]);
        else v[k] = -INFINITY;
    }
#pragma unroll
    for (int off = 16; off > 0; off >>= 1)
        mx = fmaxf(mx, __shfl_xor_sync(0xFFFFFFFFu, mx, off));
    if (lane == 0) red[wid] = mx;
    __syncthreads();
    mx = red[0];
#pragma unroll
    for (int k = 1; k < 8; k++) mx = fmaxf(mx, red[k]);
    __syncthreads();

    float sum = 0.f;
#pragma unroll
    for (int k = 0; k < 8; k++) {
        float e = __expf(v[k] - mx);   // masked: exp(-inf)=0
        v[k] = e;
        sum += e;
    }
#pragma unroll
    for (int off = 16; off > 0; off >>= 1)
        sum += __shfl_xor_sync(0xFFFFFFFFu, sum, off);
    if (lane == 0) red[wid] = sum;
    __syncthreads();
    sum = 0.f;
#pragma unroll
    for (int k = 0; k < 8; k++) sum += red[k];
    const float inv = 1.f / sum;

    if (i0 < Lpad) {
        uint4 outv;
        __half2* o2 = (__half2*)&outv;
#pragma unroll
        for (int k = 0; k < 4; k++)
            o2[k] = __floats2half2_rn(v[2 * k] * inv, v[2 * k + 1] * inv);
        *(uint4*)(row + i0) = outv;
    }
}

// ---------------------------------------------------------------------------
// Kernel 4: out = P @ V over bm in [bm_base, bm_base+grid.y), longest-first.
// ---------------------------------------------------------------------------
__global__ __launch_bounds__(NTHR, 2) void av_mma_kernel(float* __restrict__ out,
                                                         int bm_base)
{
    const int bn = blockIdx.x;
    const int bm = bm_base + (int)gridDim.y - 1 - (int)blockIdx.y;  // heavy first
    const int b  = blockIdx.z;
    const int m0 = bm << 7, n0 = bn << 7;

    float acc[4][8][4];
    ZERO_ACC(acc);
    gemm_cp(g_p + (size_t)b * S_ * S_ + (size_t)m0 * S_, S_,
            g_v + (size_t)b * D_ * S_ + (size_t)n0 * S_, S_, (bm + 1) * 4, acc);
    epilogue_f(acc, out + (size_t)b * S_ * D_ + (size_t)m0 * D_ + n0, D_);
}

// ---------------------------------------------------------------------------
extern "C" void kernel_launch(void* const* d_in, const int* in_sizes, int n_in,
                              void* d_out, int out_size)
{
    const float* query = (const float*)d_in[0];
    const float* key   = (const float*)d_in[1];
    const float* value = (const float*)d_in[2];
    // d_in[3] = causal mask (static; unused)
    const float* Wq = (const float*)d_in[4];
    const float* bq = (const float*)d_in[5];
    const float* Wk = (const float*)d_in[6];
    const float* bk = (const float*)d_in[7];
    const float* Wv = (const float*)d_in[8];
    const float* bv = (const float*)d_in[9];
    float* out = (float*)d_out;

    static cudaStream_t s2 = nullptr;
    static cudaEvent_t ev_start = nullptr, ev_wt = nullptr, ev_fork = nullptr,
                       ev_s = nullptr, ev_v = nullptr, ev_done2 = nullptr;
    if (!s2) {
        cudaFuncSetAttribute(qkv_mma_kernel,
                             cudaFuncAttributeMaxDynamicSharedMemorySize, SM_BYTES);
        cudaFuncSetAttribute(scores_mma_kernel,
                             cudaFuncAttributeMaxDynamicSharedMemorySize, SM_BYTES);
        cudaFuncSetAttribute(av_mma_kernel,
                             cudaFuncAttributeMaxDynamicSharedMemorySize, SM_BYTES);
        cudaStreamCreateWithFlags(&s2, cudaStreamNonBlocking);
        cudaEventCreateWithFlags(&ev_start, cudaEventDisableTiming);
        cudaEventCreateWithFlags(&ev_wt, cudaEventDisableTiming);
        cudaEventCreateWithFlags(&ev_fork, cudaEventDisableTiming);
        cudaEventCreateWithFlags(&ev_s, cudaEventDisableTiming);
        cudaEventCreateWithFlags(&ev_v, cudaEventDisableTiming);
        cudaEventCreateWithFlags(&ev_done2, cudaEventDisableTiming);
    }

    // Fork s2 off the origin stream so capture sees a rooted branch.
    cudaEventRecord(ev_start, 0);
    cudaStreamWaitEvent(s2, ev_start, 0);

    // s2: weight transpose (depends only on W inputs) runs under cvt.
    wt_kernel<<<dim3(32, 32, 3), dim3(256), 0, s2>>>(Wq, Wk, Wv);
    cudaEventRecord(ev_wt, s2);

    // main: input converts, then q,k projections (after wt).
    cvt_inputs_kernel<<<dim3(NROWS * D_ / (256 * 4), 1, 3), dim3(256)>>>(query, key, value);
    cudaStreamWaitEvent(0, ev_wt, 0);
    qkv_mma_kernel<<<dim3(D_ / 128, NROWS / 128, 2), dim3(NTHR), SM_BYTES>>>(
        bq, bk, bv, 0);
    cudaEventRecord(ev_fork, 0);

    // s2: v projection overlaps scores.
    cudaStreamWaitEvent(s2, ev_fork, 0);
    qkv_mma_kernel<<<dim3(D_ / 128, NROWS / 128, 1), dim3(NTHR), SM_BYTES, s2>>>(
        bq, bk, bv, 2);
    cudaEventRecord(ev_v, s2);

    // main: scores (all blocks).
    scores_mma_kernel<<<dim3(NTRI, B_), dim3(NTHR), SM_BYTES>>>();
    cudaEventRecord(ev_s, 0);

    // main: bottom half (heavy): softmax rows [1024,2048) then av bm 8..15.
    softmax_kernel<<<dim3(S_ / 2, B_), dim3(256)>>>(S_ / 2);
    cudaStreamWaitEvent(0, ev_v, 0);
    av_mma_kernel<<<dim3(D_ / 128, 8, B_), dim3(NTHR), SM_BYTES>>>(out, 8);

    // s2: top half (light): softmax rows [0,1024) then av bm 0..7.
    cudaStreamWaitEvent(s2, ev_s, 0);
    softmax_kernel<<<dim3(S_ / 2, B_), dim3(256), 0, s2>>>(0);
    av_mma_kernel<<<dim3(D_ / 128, 8, B_), dim3(NTHR), SM_BYTES, s2>>>(out, 0);
    cudaEventRecord(ev_done2, s2);

    // Rejoin into the origin stream (required for capture completeness).
    cudaStreamWaitEvent(0, ev_done2, 0);
}

// round 15
// speedup vs baseline: 1.4791x; 1.4791x over previous
#include <cuda_runtime.h>
#include <cuda_fp16.h>
#include <math.h>
#include <stdint.h>

#define B_ 8
#define S_ 2048
#define D_ 1024
#define NROWS (B_ * S_)
#define BKH 32                        // k-halves per chunk (64B per row)
#define NSTAGE 5
#define STA 40                        // halves per SMEM row (80B = 64B + 16B pad)
#define TILE_BYTES (128 * 80)         // 10240 B per operand tile
#define SM_BYTES (NSTAGE * 2 * TILE_BYTES)   // 102400 B dynamic smem
#define NTHR 128                      // 4 warps, 2x2 grid of 64x64 warp tiles
#define NTRI 136                      // 16*17/2 lower-triangular 128-blocks

// Scratch (device globals: allowed; no runtime allocation)
__device__ __half g_xq[(size_t)NROWS * D_];   // fp16 copy of query
__device__ __half g_xk[(size_t)NROWS * D_];   // fp16 copy of key
__device__ __half g_xv[(size_t)NROWS * D_];   // fp16 copy of value
__device__ __half g_q[(size_t)NROWS * D_];    // q proj [row][d]
__device__ __half g_k[(size_t)NROWS * D_];    // k proj [row][d]
__device__ __half g_v[(size_t)NROWS * D_];    // v proj TRANSPOSED [b][d][s]
__device__ __half g_p[(size_t)B_ * S_ * S_];  // scores -> probs [b][sq][sk]
__device__ __half g_wt[3 * (size_t)D_ * D_];  // W^T fp16 [which][n][k]

// ---------------------------------------------------------------------------
// PTX helpers (base ISA: cp.async / ldmatrix / mma.sync — no tcgen05)
// ---------------------------------------------------------------------------
__device__ __forceinline__ uint32_t smem_u32(const void* p) {
    uint32_t a;
    asm("{ .reg .u64 t; cvta.to.shared.u64 t, %1; cvt.u32.u64 %0, t; }"
        : "=r"(a) : "l"(p));
    return a;
}

#define CP16(dst, src)                                                        \
    asm volatile("cp.async.cg.shared.global [%0], [%1], 16;"                  \
                 :: "r"(dst), "l"(src))
#define CP_COMMIT() asm volatile("cp.async.commit_group;" ::: "memory")
#define CP_WAIT3()  asm volatile("cp.async.wait_group 3;" ::: "memory")

#define LDMX4(r0, r1, r2, r3, addr)                                           \
    asm volatile("ldmatrix.sync.aligned.m8n8.x4.shared.b16 {%0,%1,%2,%3}, [%4];" \
                 : "=r"(r0), "=r"(r1), "=r"(r2), "=r"(r3) : "r"(addr))

#define MMA_F16(c, a, b)                                                      \
    asm volatile(                                                             \
        "mma.sync.aligned.m16n8k16.row.col.f32.f16.f16.f32 "                  \
        "{%0,%1,%2,%3}, {%4,%5,%6,%7}, {%8,%9}, {%0,%1,%2,%3};"               \
        : "+f"((c)[0]), "+f"((c)[1]), "+f"((c)[2]), "+f"((c)[3])              \
        : "r"((a)[0]), "r"((a)[1]), "r"((a)[2]), "r"((a)[3]),                 \
          "r"((b)[0]), "r"((b)[1]))

#define ZERO_ACC(acc)                                                         \
    _Pragma("unroll") for (int i = 0; i < 4; i++)                             \
    _Pragma("unroll") for (int j = 0; j < 8; j++)                             \
    _Pragma("unroll") for (int k = 0; k < 4; k++) (acc)[i][j][k] = 0.f

// ---------------------------------------------------------------------------
// cp.async one chunk: A tile 128x32h + B tile 128x32h (both [row][k] fp16).
// ---------------------------------------------------------------------------
__device__ __forceinline__ void issue_tile(uint32_t smA, const __half* Ag, size_t lda,
                                           uint32_t smB, const __half* Bg, size_t ldb,
                                           int j, int tid) {
#pragma unroll
    for (int w = 0; w < 4; w++) {
        const int lin = tid + (w << 7);          // 0..511
        const int r = lin >> 2, q = lin & 3;
        CP16(smA + r * 80 + (q << 4), Ag + (size_t)r * lda + j * BKH + (q << 3));
        CP16(smB + r * 80 + (q << 4), Bg + (size_t)r * ldb + j * BKH + (q << 3));
    }
}

// ---------------------------------------------------------------------------
// LDSM one k16 step's fragments for a 64x64 warp tile.
// ---------------------------------------------------------------------------
__device__ __forceinline__ void ldsm_frags(uint32_t smA, uint32_t smB, int k16,
                                           int wm, int wn, int lane,
                                           uint32_t af[4][4], uint32_t bf[8][2]) {
    const int a_row = lane & 15;
    const int a_k8  = ((lane >> 4) & 1) << 3;
    const int b_row = (lane & 7) + (((lane >> 4) & 1) << 3);
    const int b_k8  = ((lane >> 3) & 1) << 3;
#pragma unroll
    for (int im = 0; im < 4; im++) {
        uint32_t addr = smA +
            (uint32_t)(((wm + (im << 4) + a_row) * STA + k16 + a_k8) << 1);
        LDMX4(af[im][0], af[im][1], af[im][2], af[im][3], addr);
    }
#pragma unroll
    for (int ip = 0; ip < 4; ip++) {
        uint32_t addr = smB +
            (uint32_t)(((wn + (ip << 4) + b_row) * STA + k16 + b_k8) << 1);
        LDMX4(bf[2 * ip][0], bf[2 * ip][1], bf[2 * ip + 1][0], bf[2 * ip + 1][1], addr);
    }
}

__device__ __forceinline__ void mma_all(float acc[4][8][4],
                                        uint32_t af[4][4], uint32_t bf[8][2]) {
#pragma unroll
    for (int im = 0; im < 4; im++)
#pragma unroll
        for (int in = 0; in < 8; in++) MMA_F16(acc[im][in], af[im], bf[in]);
}

// ---------------------------------------------------------------------------
// CUTLASS-style 5-stage mainloop, chunk K=32h (2 k16 steps), frag ping-pong.
// (R8/R10 schedule — verified best of family; do not touch.)
// ---------------------------------------------------------------------------
__device__ __forceinline__ void gemm_cp(const __half* Ag, size_t lda,
                                        const __half* Bg, size_t ldb, int KT,
                                        float acc[4][8][4]) {
    extern __shared__ __half smh[];
    const int tid = threadIdx.x, lane = tid & 31, warp = tid >> 5;
    const int wm = (warp >> 1) << 6, wn = (warp & 1) << 6;
    const uint32_t smb = smem_u32(smh);

#pragma unroll
    for (int s = 0; s < 4; s++) {
        if (s < KT)
            issue_tile(smb + s * 2 * TILE_BYTES, Ag, lda,
                       smb + s * 2 * TILE_BYTES + TILE_BYTES, Bg, ldb, s, tid);
        CP_COMMIT();
    }
    CP_WAIT3();
    __syncthreads();

    uint32_t af[2][4][4], bf[2][8][2];
    ldsm_frags(smb, smb + TILE_BYTES, 0, wm, wn, lane, af[0], bf[0]);

    for (int j = 0; j < KT; ++j) {
        const uint32_t sA = smb + (j % NSTAGE) * 2 * TILE_BYTES;
        ldsm_frags(sA, sA + TILE_BYTES, 16, wm, wn, lane, af[1], bf[1]);

        const int jn = j + 4;
        if (jn < KT) {
            const uint32_t sN = smb + (jn % NSTAGE) * 2 * TILE_BYTES;
            issue_tile(sN, Ag, lda, sN + TILE_BYTES, Bg, ldb, jn, tid);
        }
        CP_COMMIT();

        mma_all(acc, af[0], bf[0]);            // step0 MMAs

        CP_WAIT3();
        __syncthreads();

        if (j + 1 < KT) {
            const uint32_t sB = smb + ((j + 1) % NSTAGE) * 2 * TILE_BYTES;
            ldsm_frags(sB, sB + TILE_BYTES, 0, wm, wn, lane, af[0], bf[0]);
        }
        mma_all(acc, af[1], bf[1]);            // step1 MMAs (frags pre-loaded)
    }
}

// ---------------------------------------------------------------------------
// Epilogues
// ---------------------------------------------------------------------------
__device__ __forceinline__ void epilogue_h(float acc[4][8][4], __half* out, size_t ld,
                                           const float* bias, float scale) {
    const int lane = threadIdx.x & 31, warp = threadIdx.x >> 5;
    const int g = lane >> 2, t = lane & 3;
    const int wm = (warp >> 1) << 6, wn = (warp & 1) << 6;
#pragma unroll
    for (int im = 0; im < 4; im++) {
#pragma unroll
        for (int in = 0; in < 8; in++) {
            const int r0 = wm + (im << 4) + g;
            const int c = wn + (in << 3) + (t << 1);
            const float b0 = bias ? bias[c] : 0.f;
            const float b1 = bias ? bias[c + 1] : 0.f;
            *(__half2*)(out + (size_t)r0 * ld + c) =
                __floats2half2_rn(acc[im][in][0] * scale + b0,
                                  acc[im][in][1] * scale + b1);
            *(__half2*)(out + (size_t)(r0 + 8) * ld + c) =
                __floats2half2_rn(acc[im][in][2] * scale + b0,
                                  acc[im][in][3] * scale + b1);
        }
    }
}

__device__ __forceinline__ void epilogue_f(float acc[4][8][4], float* out, size_t ld) {
    const int lane = threadIdx.x & 31, warp = threadIdx.x >> 5;
    const int g = lane >> 2, t = lane & 3;
    const int wm = (warp >> 1) << 6, wn = (warp & 1) << 6;
#pragma unroll
    for (int im = 0; im < 4; im++) {
#pragma unroll
        for (int in = 0; in < 8; in++) {
            const int r0 = wm + (im << 4) + g;
            const int c = wn + (in << 3) + (t << 1);
            *(float2*)(out + (size_t)r0 * ld + c) =
                make_float2(acc[im][in][0], acc[im][in][1]);
            *(float2*)(out + (size_t)(r0 + 8) * ld + c) =
                make_float2(acc[im][in][2], acc[im][in][3]);
        }
    }
}

// Transposed store for V: vt is [D][S] for this batch (fp16).
__device__ __forceinline__ void epilogue_vt(float acc[4][8][4], __half* vt,
                                            int mloc, int n0, const float* bias) {
    const int lane = threadIdx.x & 31, warp = threadIdx.x >> 5;
    const int g = lane >> 2, t = lane & 3;
    const int wm = (warp >> 1) << 6, wn = (warp & 1) << 6;
#pragma unroll
    for (int im = 0; im < 4; im++) {
#pragma unroll
        for (int in = 0; in < 8; in++) {
            const int r = mloc + wm + (im << 4) + g;
            const int c = n0 + wn + (in << 3) + (t << 1);
            const float b0 = bias[c], b1 = bias[c + 1];
            vt[(size_t)c * S_ + r]           = __float2half_rn(acc[im][in][0] + b0);
            vt[(size_t)(c + 1) * S_ + r]     = __float2half_rn(acc[im][in][1] + b1);
            vt[(size_t)c * S_ + r + 8]       = __float2half_rn(acc[im][in][2] + b0);
            vt[(size_t)(c + 1) * S_ + r + 8] = __float2half_rn(acc[im][in][3] + b1);
        }
    }
}

// ---------------------------------------------------------------------------
// Kernel 0a: fp32 -> fp16 convert of raw query/key/value
// ---------------------------------------------------------------------------
__global__ __launch_bounds__(256) void cvt_inputs_kernel(
    const float* __restrict__ q, const float* __restrict__ k,
    const float* __restrict__ v) {
    const int z = blockIdx.z;
    const float* src = (z == 0) ? q : (z == 1) ? k : v;
    __half* dst = (z == 0) ? g_xq : (z == 1) ? g_xk : g_xv;
    const size_t i = ((size_t)blockIdx.x * 256 + threadIdx.x) * 4;
    float4 f = *(const float4*)(src + i);
    __half2* d2 = (__half2*)(dst + i);
    d2[0] = __floats2half2_rn(f.x, f.y);
    d2[1] = __floats2half2_rn(f.z, f.w);
}

// ---------------------------------------------------------------------------
// Kernel 0b: W ([k][n] fp32) -> g_wt ([n][k] fp16). Depends only on W inputs.
// ---------------------------------------------------------------------------
__global__ __launch_bounds__(256) void wt_kernel(const float* __restrict__ Wq,
                                                 const float* __restrict__ Wk,
                                                 const float* __restrict__ Wv) {
    const int z = blockIdx.z;
    const float* W = (z == 0) ? Wq : (z == 1) ? Wk : Wv;
    __half* WT = g_wt + (size_t)z * D_ * D_;
    __shared__ float t[32][33];
    const int tx = threadIdx.x & 31, ty = threadIdx.x >> 5;
    const int x0 = blockIdx.x << 5, y0 = blockIdx.y << 5;
#pragma unroll
    for (int i = 0; i < 4; i++)
        t[ty + i * 8][tx] = W[(size_t)(y0 + ty + i * 8) * D_ + x0 + tx];
    __syncthreads();
#pragma unroll
    for (int i = 0; i < 4; i++)
        WT[(size_t)(x0 + ty + i * 8) * D_ + y0 + tx] = __float2half_rn(t[tx][ty + i * 8]);
}

// ---------------------------------------------------------------------------
// Kernel 1: QKV projection  C = X @ W + b.  which = blockIdx.z + which_base.
// ---------------------------------------------------------------------------
__global__ __launch_bounds__(NTHR, 2) void qkv_mma_kernel(
    const float* __restrict__ bq, const float* __restrict__ bk,
    const float* __restrict__ bv, int which_base)
{
    const int which = blockIdx.z + which_base;
    const __half* A   = (which == 0) ? g_xq : (which == 1) ? g_xk : g_xv;
    const float* bias = (which == 0) ? bq   : (which == 1) ? bk   : bv;

    const int m0 = blockIdx.y << 7, n0 = blockIdx.x << 7;
    float acc[4][8][4];
    ZERO_ACC(acc);
    gemm_cp(A + (size_t)m0 * D_, D_,
            g_wt + (size_t)which * D_ * D_ + (size_t)n0 * D_, D_, D_ / BKH, acc);

    if (which == 2) {
        const int b = m0 >> 11;
        epilogue_vt(acc, g_v + (size_t)b * D_ * S_, m0 & (S_ - 1), n0, bias);
    } else {
        __half* C = (which == 0) ? g_q : g_k;
        epilogue_h(acc, C + (size_t)m0 * D_ + n0, D_, bias + n0, 1.0f);
    }
}

// ---------------------------------------------------------------------------
// Kernel 2: scores = (Q @ K^T)/32 — triangular-packed grid, no empty CTAs.
// ---------------------------------------------------------------------------
__global__ __launch_bounds__(NTHR, 2) void scores_mma_kernel()
{
    const int i = blockIdx.x;
    int bm = (int)((sqrtf(8.f * (float)i + 1.f) - 1.f) * 0.5f);
    if ((bm + 1) * (bm + 2) / 2 <= i) bm++;
    else if (bm * (bm + 1) / 2 > i) bm--;
    const int bn = i - bm * (bm + 1) / 2;
    const int b = blockIdx.y;
    const int m0 = bm << 7, n0 = bn << 7;

    float acc[4][8][4];
    ZERO_ACC(acc);
    gemm_cp(g_q + (size_t)b * S_ * D_ + (size_t)m0 * D_, D_,
            g_k + (size_t)b * S_ * D_ + (size_t)n0 * D_, D_, D_ / BKH, acc);
    epilogue_h(acc, g_p + (size_t)b * S_ * S_ + (size_t)m0 * S_ + n0, S_,
               nullptr, 0.03125f);
}

// ---------------------------------------------------------------------------
// Kernel 3: causal row softmax, vectorized (uint4 of 8 halves per thread).
// ---------------------------------------------------------------------------
__global__ __launch_bounds__(256) void softmax_kernel()
{
    const int m = blockIdx.x;
    const int b = blockIdx.y;
    __half* row = g_p + ((size_t)b * S_ + m) * S_;
    const int L = m + 1;
    const int Lpad = ((m >> 7) + 1) << 7;

    const int tid = threadIdx.x;
    const int lane = tid & 31, wid = tid >> 5;
    const int i0 = tid << 3;

    __shared__ float red[8];

    uint4 raw = *(const uint4*)(row + i0);
    const __half2* h2 = (const __half2*)&raw;
    float v[8];
#pragma unroll
    for (int k = 0; k < 4; k++) {
        float2 f = __half22float2(h2[k]);
        v[2 * k] = f.x;
        v[2 * k + 1] = f.y;
    }

    float mx = -INFINITY;
#pragma unroll
    for (int k = 0; k < 8; k++) {
        if (i0 + k < L) mx = fmaxf(mx, v[k]);
        else v[k] = -INFINITY;
    }
#pragma unroll
    for (int off = 16; off > 0; off >>= 1)
        mx = fmaxf(mx, __shfl_xor_sync(0xFFFFFFFFu, mx, off));
    if (lane == 0) red[wid] = mx;
    __syncthreads();
    mx = red[0];
#pragma unroll
    for (int k = 1; k < 8; k++) mx = fmaxf(mx, red[k]);
    __syncthreads();

    float sum = 0.f;
#pragma unroll
    for (int k = 0; k < 8; k++) {
        float e = __expf(v[k] - mx);   // masked: exp(-inf)=0
        v[k] = e;
        sum += e;
    }
#pragma unroll
    for (int off = 16; off > 0; off >>= 1)
        sum += __shfl_xor_sync(0xFFFFFFFFu, sum, off);
    if (lane == 0) red[wid] = sum;
    __syncthreads();
    sum = 0.f;
#pragma unroll
    for (int k = 0; k < 8; k++) sum += red[k];
    const float inv = 1.f / sum;

    if (i0 < Lpad) {
        uint4 outv;
        __half2* o2 = (__half2*)&outv;
#pragma unroll
        for (int k = 0; k < 4; k++)
            o2[k] = __floats2half2_rn(v[2 * k] * inv, v[2 * k + 1] * inv);
        *(uint4*)(row + i0) = outv;
    }
}

// ---------------------------------------------------------------------------
// Kernel 4: out = P @ V, longest-first over bm.
// ---------------------------------------------------------------------------
__global__ __launch_bounds__(NTHR, 2) void av_mma_kernel(float* __restrict__ out)
{
    const int bn = blockIdx.x;
    const int bm = (int)gridDim.y - 1 - (int)blockIdx.y;   // heavy first
    const int b  = blockIdx.z;
    const int m0 = bm << 7, n0 = bn << 7;

    float acc[4][8][4];
    ZERO_ACC(acc);
    gemm_cp(g_p + (size_t)b * S_ * S_ + (size_t)m0 * S_, S_,
            g_v + (size_t)b * D_ * S_ + (size_t)n0 * S_, S_, (bm + 1) * 4, acc);
    epilogue_f(acc, out + (size_t)b * S_ * D_ + (size_t)m0 * D_ + n0, D_);
}

// ---------------------------------------------------------------------------
extern "C" void kernel_launch(void* const* d_in, const int* in_sizes, int n_in,
                              void* d_out, int out_size)
{
    const float* query = (const float*)d_in[0];
    const float* key   = (const float*)d_in[1];
    const float* value = (const float*)d_in[2];
    // d_in[3] = causal mask (static; unused)
    const float* Wq = (const float*)d_in[4];
    const float* bq = (const float*)d_in[5];
    const float* Wk = (const float*)d_in[6];
    const float* bk = (const float*)d_in[7];
    const float* Wv = (const float*)d_in[8];
    const float* bv = (const float*)d_in[9];
    float* out = (float*)d_out;

    static cudaStream_t s2 = nullptr;
    static cudaEvent_t ev_start = nullptr, ev_wt = nullptr,
                       ev_fork = nullptr, ev_join = nullptr;
    if (!s2) {
        cudaFuncSetAttribute(qkv_mma_kernel,
                             cudaFuncAttributeMaxDynamicSharedMemorySize, SM_BYTES);
        cudaFuncSetAttribute(scores_mma_kernel,
                             cudaFuncAttributeMaxDynamicSharedMemorySize, SM_BYTES);
        cudaFuncSetAttribute(av_mma_kernel,
                             cudaFuncAttributeMaxDynamicSharedMemorySize, SM_BYTES);
        cudaStreamCreateWithFlags(&s2, cudaStreamNonBlocking);
        cudaEventCreateWithFlags(&ev_start, cudaEventDisableTiming);
        cudaEventCreateWithFlags(&ev_wt, cudaEventDisableTiming);
        cudaEventCreateWithFlags(&ev_fork, cudaEventDisableTiming);
        cudaEventCreateWithFlags(&ev_join, cudaEventDisableTiming);
    }

    // Root s2 off the origin stream (required under capture).
    cudaEventRecord(ev_start, 0);
    cudaStreamWaitEvent(s2, ev_start, 0);

    // s2: weight transpose (W inputs only) runs concurrent with cvt.
    wt_kernel<<<dim3(32, 32, 3), dim3(256), 0, s2>>>(Wq, Wk, Wv);
    cudaEventRecord(ev_wt, s2);

    // main: input converts.
    cvt_inputs_kernel<<<dim3(NROWS * D_ / (256 * 4), 1, 3), dim3(256)>>>(query, key, value);
    cudaStreamWaitEvent(0, ev_wt, 0);

    // main: q,k projections.
    qkv_mma_kernel<<<dim3(D_ / 128, NROWS / 128, 2), dim3(NTHR), SM_BYTES>>>(
        bq, bk, bv, 0);

    // Fork: v projection on s2, overlapping scores+softmax (R13 pattern).
    cudaEventRecord(ev_fork, 0);
    cudaStreamWaitEvent(s2, ev_fork, 0);
    qkv_mma_kernel<<<dim3(D_ / 128, NROWS / 128, 1), dim3(NTHR), SM_BYTES, s2>>>(
        bq, bk, bv, 2);

    // main: scores + softmax (concurrent with v projection).
    scores_mma_kernel<<<dim3(NTRI, B_), dim3(NTHR), SM_BYTES>>>();
    softmax_kernel<<<dim3(S_, B_), dim3(256)>>>();

    // Join: av needs both P (main) and V^T (s2).
    cudaEventRecord(ev_join, s2);
    cudaStreamWaitEvent(0, ev_join, 0);

    av_mma_kernel<<<dim3(D_ / 128, S_ / 128, B_), dim3(NTHR), SM_BYTES>>>(out);
}

// round 16
// speedup vs baseline: 1.4865x; 1.0050x over previous
#include <cuda_runtime.h>
#include <cuda_fp16.h>
#include <math.h>
#include <stdint.h>

#define B_ 8
#define S_ 2048
#define D_ 1024
#define NROWS (B_ * S_)
#define BKH 32                        // k-halves per chunk (64B per row)
#define NSTAGE 5
#define STA 40                        // halves per SMEM row (80B = 64B + 16B pad)
#define TILE_BYTES (128 * 80)         // 10240 B per operand tile
#define SM_BYTES (NSTAGE * 2 * TILE_BYTES)   // 102400 B dynamic smem
#define NTHR 128                      // 4 warps, 2x2 grid of 64x64 warp tiles
#define NTRI 136                      // 16*17/2 lower-triangular 128-blocks

// Scratch (device globals: allowed; no runtime allocation)
__device__ __half g_xq[(size_t)NROWS * D_];   // fp16 copy of query
__device__ __half g_xk[(size_t)NROWS * D_];   // fp16 copy of key
__device__ __half g_xv[(size_t)NROWS * D_];   // fp16 copy of value
__device__ __half g_q[(size_t)NROWS * D_];    // q proj [row][d]
__device__ __half g_k[(size_t)NROWS * D_];    // k proj [row][d]
__device__ __half g_v[(size_t)NROWS * D_];    // v proj TRANSPOSED [b][d][s]
__device__ __half g_p[(size_t)B_ * S_ * S_];  // scores -> probs [b][sq][sk]
__device__ __half g_wt[3 * (size_t)D_ * D_];  // W^T fp16 [which][n][k]

// ---------------------------------------------------------------------------
// PTX helpers (base ISA: cp.async / ldmatrix / mma.sync — no tcgen05)
// ---------------------------------------------------------------------------
__device__ __forceinline__ uint32_t smem_u32(const void* p) {
    uint32_t a;
    asm("{ .reg .u64 t; cvta.to.shared.u64 t, %1; cvt.u32.u64 %0, t; }"
        : "=r"(a) : "l"(p));
    return a;
}

#define CP16(dst, src)                                                        \
    asm volatile("cp.async.cg.shared.global [%0], [%1], 16;"                  \
                 :: "r"(dst), "l"(src))
#define CP_COMMIT() asm volatile("cp.async.commit_group;" ::: "memory")
#define CP_WAIT3()  asm volatile("cp.async.wait_group 3;" ::: "memory")

#define LDMX4(r0, r1, r2, r3, addr)                                           \
    asm volatile("ldmatrix.sync.aligned.m8n8.x4.shared.b16 {%0,%1,%2,%3}, [%4];" \
                 : "=r"(r0), "=r"(r1), "=r"(r2), "=r"(r3) : "r"(addr))

#define MMA_F16(c, a, b)                                                      \
    asm volatile(                                                             \
        "mma.sync.aligned.m16n8k16.row.col.f32.f16.f16.f32 "                  \
        "{%0,%1,%2,%3}, {%4,%5,%6,%7}, {%8,%9}, {%0,%1,%2,%3};"               \
        : "+f"((c)[0]), "+f"((c)[1]), "+f"((c)[2]), "+f"((c)[3])              \
        : "r"((a)[0]), "r"((a)[1]), "r"((a)[2]), "r"((a)[3]),                 \
          "r"((b)[0]), "r"((b)[1]))

#define ZERO_ACC(acc)                                                         \
    _Pragma("unroll") for (int i = 0; i < 4; i++)                             \
    _Pragma("unroll") for (int j = 0; j < 8; j++)                             \
    _Pragma("unroll") for (int k = 0; k < 4; k++) (acc)[i][j][k] = 0.f

// ---------------------------------------------------------------------------
// cp.async one chunk: A tile 128x32h + B tile 128x32h (both [row][k] fp16).
// ---------------------------------------------------------------------------
__device__ __forceinline__ void issue_tile(uint32_t smA, const __half* Ag, size_t lda,
                                           uint32_t smB, const __half* Bg, size_t ldb,
                                           int j, int tid) {
#pragma unroll
    for (int w = 0; w < 4; w++) {
        const int lin = tid + (w << 7);          // 0..511
        const int r = lin >> 2, q = lin & 3;
        CP16(smA + r * 80 + (q << 4), Ag + (size_t)r * lda + j * BKH + (q << 3));
        CP16(smB + r * 80 + (q << 4), Bg + (size_t)r * ldb + j * BKH + (q << 3));
    }
}

// ---------------------------------------------------------------------------
// LDSM one k16 step's fragments for a 64x64 warp tile.
// ---------------------------------------------------------------------------
__device__ __forceinline__ void ldsm_frags(uint32_t smA, uint32_t smB, int k16,
                                           int wm, int wn, int lane,
                                           uint32_t af[4][4], uint32_t bf[8][2]) {
    const int a_row = lane & 15;
    const int a_k8  = ((lane >> 4) & 1) << 3;
    const int b_row = (lane & 7) + (((lane >> 4) & 1) << 3);
    const int b_k8  = ((lane >> 3) & 1) << 3;
#pragma unroll
    for (int im = 0; im < 4; im++) {
        uint32_t addr = smA +
            (uint32_t)(((wm + (im << 4) + a_row) * STA + k16 + a_k8) << 1);
        LDMX4(af[im][0], af[im][1], af[im][2], af[im][3], addr);
    }
#pragma unroll
    for (int ip = 0; ip < 4; ip++) {
        uint32_t addr = smB +
            (uint32_t)(((wn + (ip << 4) + b_row) * STA + k16 + b_k8) << 1);
        LDMX4(bf[2 * ip][0], bf[2 * ip][1], bf[2 * ip + 1][0], bf[2 * ip + 1][1], addr);
    }
}

__device__ __forceinline__ void mma_all(float acc[4][8][4],
                                        uint32_t af[4][4], uint32_t bf[8][2]) {
#pragma unroll
    for (int im = 0; im < 4; im++)
#pragma unroll
        for (int in = 0; in < 8; in++) MMA_F16(acc[im][in], af[im], bf[in]);
}

// ---------------------------------------------------------------------------
// CUTLASS-style 5-stage mainloop, chunk K=32h (2 k16 steps), frag ping-pong.
// (R8/R10 schedule — verified best of family; do not touch.)
// ---------------------------------------------------------------------------
__device__ __forceinline__ void gemm_cp(const __half* Ag, size_t lda,
                                        const __half* Bg, size_t ldb, int KT,
                                        float acc[4][8][4]) {
    extern __shared__ __half smh[];
    const int tid = threadIdx.x, lane = tid & 31, warp = tid >> 5;
    const int wm = (warp >> 1) << 6, wn = (warp & 1) << 6;
    const uint32_t smb = smem_u32(smh);

#pragma unroll
    for (int s = 0; s < 4; s++) {
        if (s < KT)
            issue_tile(smb + s * 2 * TILE_BYTES, Ag, lda,
                       smb + s * 2 * TILE_BYTES + TILE_BYTES, Bg, ldb, s, tid);
        CP_COMMIT();
    }
    CP_WAIT3();
    __syncthreads();

    uint32_t af[2][4][4], bf[2][8][2];
    ldsm_frags(smb, smb + TILE_BYTES, 0, wm, wn, lane, af[0], bf[0]);

    for (int j = 0; j < KT; ++j) {
        const uint32_t sA = smb + (j % NSTAGE) * 2 * TILE_BYTES;
        ldsm_frags(sA, sA + TILE_BYTES, 16, wm, wn, lane, af[1], bf[1]);

        const int jn = j + 4;
        if (jn < KT) {
            const uint32_t sN = smb + (jn % NSTAGE) * 2 * TILE_BYTES;
            issue_tile(sN, Ag, lda, sN + TILE_BYTES, Bg, ldb, jn, tid);
        }
        CP_COMMIT();

        mma_all(acc, af[0], bf[0]);            // step0 MMAs

        CP_WAIT3();
        __syncthreads();

        if (j + 1 < KT) {
            const uint32_t sB = smb + ((j + 1) % NSTAGE) * 2 * TILE_BYTES;
            ldsm_frags(sB, sB + TILE_BYTES, 0, wm, wn, lane, af[0], bf[0]);
        }
        mma_all(acc, af[1], bf[1]);            // step1 MMAs (frags pre-loaded)
    }
}

// ---------------------------------------------------------------------------
// Epilogues
// ---------------------------------------------------------------------------
__device__ __forceinline__ void epilogue_h(float acc[4][8][4], __half* out, size_t ld,
                                           const float* bias, float scale) {
    const int lane = threadIdx.x & 31, warp = threadIdx.x >> 5;
    const int g = lane >> 2, t = lane & 3;
    const int wm = (warp >> 1) << 6, wn = (warp & 1) << 6;
#pragma unroll
    for (int im = 0; im < 4; im++) {
#pragma unroll
        for (int in = 0; in < 8; in++) {
            const int r0 = wm + (im << 4) + g;
            const int c = wn + (in << 3) + (t << 1);
            const float b0 = bias ? bias[c] : 0.f;
            const float b1 = bias ? bias[c + 1] : 0.f;
            *(__half2*)(out + (size_t)r0 * ld + c) =
                __floats2half2_rn(acc[im][in][0] * scale + b0,
                                  acc[im][in][1] * scale + b1);
            *(__half2*)(out + (size_t)(r0 + 8) * ld + c) =
                __floats2half2_rn(acc[im][in][2] * scale + b0,
                                  acc[im][in][3] * scale + b1);
        }
    }
}

__device__ __forceinline__ void epilogue_f(float acc[4][8][4], float* out, size_t ld) {
    const int lane = threadIdx.x & 31, warp = threadIdx.x >> 5;
    const int g = lane >> 2, t = lane & 3;
    const int wm = (warp >> 1) << 6, wn = (warp & 1) << 6;
#pragma unroll
    for (int im = 0; im < 4; im++) {
#pragma unroll
        for (int in = 0; in < 8; in++) {
            const int r0 = wm + (im << 4) + g;
            const int c = wn + (in << 3) + (t << 1);
            *(float2*)(out + (size_t)r0 * ld + c) =
                make_float2(acc[im][in][0], acc[im][in][1]);
            *(float2*)(out + (size_t)(r0 + 8) * ld + c) =
                make_float2(acc[im][in][2], acc[im][in][3]);
        }
    }
}

// Transposed store for V: vt is [D][S] for this batch (fp16).
__device__ __forceinline__ void epilogue_vt(float acc[4][8][4], __half* vt,
                                            int mloc, int n0, const float* bias) {
    const int lane = threadIdx.x & 31, warp = threadIdx.x >> 5;
    const int g = lane >> 2, t = lane & 3;
    const int wm = (warp >> 1) << 6, wn = (warp & 1) << 6;
#pragma unroll
    for (int im = 0; im < 4; im++) {
#pragma unroll
        for (int in = 0; in < 8; in++) {
            const int r = mloc + wm + (im << 4) + g;
            const int c = n0 + wn + (in << 3) + (t << 1);
            const float b0 = bias[c], b1 = bias[c + 1];
            vt[(size_t)c * S_ + r]           = __float2half_rn(acc[im][in][0] + b0);
            vt[(size_t)(c + 1) * S_ + r]     = __float2half_rn(acc[im][in][1] + b1);
            vt[(size_t)c * S_ + r + 8]       = __float2half_rn(acc[im][in][2] + b0);
            vt[(size_t)(c + 1) * S_ + r + 8] = __float2half_rn(acc[im][in][3] + b1);
        }
    }
}

// ---------------------------------------------------------------------------
// Kernel 0a: fp32 -> fp16 convert; z selects tensor (grid.z slice via base).
// ---------------------------------------------------------------------------
__global__ __launch_bounds__(256) void cvt_inputs_kernel(
    const float* __restrict__ q, const float* __restrict__ k,
    const float* __restrict__ v, int z_base) {
    const int z = blockIdx.z + z_base;
    const float* src = (z == 0) ? q : (z == 1) ? k : v;
    __half* dst = (z == 0) ? g_xq : (z == 1) ? g_xk : g_xv;
    const size_t i = ((size_t)blockIdx.x * 256 + threadIdx.x) * 4;
    float4 f = *(const float4*)(src + i);
    __half2* d2 = (__half2*)(dst + i);
    d2[0] = __floats2half2_rn(f.x, f.y);
    d2[1] = __floats2half2_rn(f.z, f.w);
}

// ---------------------------------------------------------------------------
// Kernel 0b: W ([k][n] fp32) -> g_wt ([n][k] fp16). Depends only on W inputs.
// ---------------------------------------------------------------------------
__global__ __launch_bounds__(256) void wt_kernel(const float* __restrict__ Wq,
                                                 const float* __restrict__ Wk,
                                                 const float* __restrict__ Wv) {
    const int z = blockIdx.z;
    const float* W = (z == 0) ? Wq : (z == 1) ? Wk : Wv;
    __half* WT = g_wt + (size_t)z * D_ * D_;
    __shared__ float t[32][33];
    const int tx = threadIdx.x & 31, ty = threadIdx.x >> 5;
    const int x0 = blockIdx.x << 5, y0 = blockIdx.y << 5;
#pragma unroll
    for (int i = 0; i < 4; i++)
        t[ty + i * 8][tx] = W[(size_t)(y0 + ty + i * 8) * D_ + x0 + tx];
    __syncthreads();
#pragma unroll
    for (int i = 0; i < 4; i++)
        WT[(size_t)(x0 + ty + i * 8) * D_ + y0 + tx] = __float2half_rn(t[tx][ty + i * 8]);
}

// ---------------------------------------------------------------------------
// Kernel 1: QKV projection  C = X @ W + b.  which = blockIdx.z + which_base.
// ---------------------------------------------------------------------------
__global__ __launch_bounds__(NTHR, 2) void qkv_mma_kernel(
    const float* __restrict__ bq, const float* __restrict__ bk,
    const float* __restrict__ bv, int which_base)
{
    const int which = blockIdx.z + which_base;
    const __half* A   = (which == 0) ? g_xq : (which == 1) ? g_xk : g_xv;
    const float* bias = (which == 0) ? bq   : (which == 1) ? bk   : bv;

    const int m0 = blockIdx.y << 7, n0 = blockIdx.x << 7;
    float acc[4][8][4];
    ZERO_ACC(acc);
    gemm_cp(A + (size_t)m0 * D_, D_,
            g_wt + (size_t)which * D_ * D_ + (size_t)n0 * D_, D_, D_ / BKH, acc);

    if (which == 2) {
        const int b = m0 >> 11;
        epilogue_vt(acc, g_v + (size_t)b * D_ * S_, m0 & (S_ - 1), n0, bias);
    } else {
        __half* C = (which == 0) ? g_q : g_k;
        epilogue_h(acc, C + (size_t)m0 * D_ + n0, D_, bias + n0, 1.0f);
    }
}

// ---------------------------------------------------------------------------
// Kernel 2: scores = (Q @ K^T)/32 — triangular-packed grid, no empty CTAs.
// ---------------------------------------------------------------------------
__global__ __launch_bounds__(NTHR, 2) void scores_mma_kernel()
{
    const int i = blockIdx.x;
    int bm = (int)((sqrtf(8.f * (float)i + 1.f) - 1.f) * 0.5f);
    if ((bm + 1) * (bm + 2) / 2 <= i) bm++;
    else if (bm * (bm + 1) / 2 > i) bm--;
    const int bn = i - bm * (bm + 1) / 2;
    const int b = blockIdx.y;
    const int m0 = bm << 7, n0 = bn << 7;

    float acc[4][8][4];
    ZERO_ACC(acc);
    gemm_cp(g_q + (size_t)b * S_ * D_ + (size_t)m0 * D_, D_,
            g_k + (size_t)b * S_ * D_ + (size_t)n0 * D_, D_, D_ / BKH, acc);
    epilogue_h(acc, g_p + (size_t)b * S_ * S_ + (size_t)m0 * S_ + n0, S_,
               nullptr, 0.03125f);
}

// ---------------------------------------------------------------------------
// Kernel 3: causal row softmax, vectorized; loads suppressed beyond Lpad.
// ---------------------------------------------------------------------------
__global__ __launch_bounds__(256) void softmax_kernel()
{
    const int m = blockIdx.x;
    const int b = blockIdx.y;
    __half* row = g_p + ((size_t)b * S_ + m) * S_;
    const int L = m + 1;
    const int Lpad = ((m >> 7) + 1) << 7;

    const int tid = threadIdx.x;
    const int lane = tid & 31, wid = tid >> 5;
    const int i0 = tid << 3;
    const bool live = (i0 < Lpad);

    __shared__ float red[8];

    float v[8];
    if (live) {
        uint4 raw = *(const uint4*)(row + i0);
        const __half2* h2 = (const __half2*)&raw;
#pragma unroll
        for (int k = 0; k < 4; k++) {
            float2 f = __half22float2(h2[k]);
            v[2 * k] = f.x;
            v[2 * k + 1] = f.y;
        }
    } else {
#pragma unroll
        for (int k = 0; k < 8; k++) v[k] = -INFINITY;
    }

    float mx = -INFINITY;
#pragma unroll
    for (int k = 0; k < 8; k++) {
        if (i0 + k < L) mx = fmaxf(mx, v[k]);
        else v[k] = -INFINITY;
    }
#pragma unroll
    for (int off = 16; off > 0; off >>= 1)
        mx = fmaxf(mx, __shfl_xor_sync(0xFFFFFFFFu, mx, off));
    if (lane == 0) red[wid] = mx;
    __syncthreads();
    mx = red[0];
#pragma unroll
    for (int k = 1; k < 8; k++) mx = fmaxf(mx, red[k]);
    __syncthreads();

    float sum = 0.f;
#pragma unroll
    for (int k = 0; k < 8; k++) {
        float e = __expf(v[k] - mx);   // masked: exp(-inf)=0
        v[k] = e;
        sum += e;
    }
#pragma unroll
    for (int off = 16; off > 0; off >>= 1)
        sum += __shfl_xor_sync(0xFFFFFFFFu, sum, off);
    if (lane == 0) red[wid] = sum;
    __syncthreads();
    sum = 0.f;
#pragma unroll
    for (int k = 0; k < 8; k++) sum += red[k];
    const float inv = 1.f / sum;

    if (live) {
        uint4 outv;
        __half2* o2 = (__half2*)&outv;
#pragma unroll
        for (int k = 0; k < 4; k++)
            o2[k] = __floats2half2_rn(v[2 * k] * inv, v[2 * k + 1] * inv);
        *(uint4*)(row + i0) = outv;
    }
}

// ---------------------------------------------------------------------------
// Kernel 4: out = P @ V, longest-first over bm.
// ---------------------------------------------------------------------------
__global__ __launch_bounds__(NTHR, 2) void av_mma_kernel(float* __restrict__ out)
{
    const int bn = blockIdx.x;
    const int bm = (int)gridDim.y - 1 - (int)blockIdx.y;   // heavy first
    const int b  = blockIdx.z;
    const int m0 = bm << 7, n0 = bn << 7;

    float acc[4][8][4];
    ZERO_ACC(acc);
    gemm_cp(g_p + (size_t)b * S_ * S_ + (size_t)m0 * S_, S_,
            g_v + (size_t)b * D_ * S_ + (size_t)n0 * S_, S_, (bm + 1) * 4, acc);
    epilogue_f(acc, out + (size_t)b * S_ * D_ + (size_t)m0 * D_ + n0, D_);
}

// ---------------------------------------------------------------------------
extern "C" void kernel_launch(void* const* d_in, const int* in_sizes, int n_in,
                              void* d_out, int out_size)
{
    const float* query = (const float*)d_in[0];
    const float* key   = (const float*)d_in[1];
    const float* value = (const float*)d_in[2];
    // d_in[3] = causal mask (static; unused)
    const float* Wq = (const float*)d_in[4];
    const float* bq = (const float*)d_in[5];
    const float* Wk = (const float*)d_in[6];
    const float* bk = (const float*)d_in[7];
    const float* Wv = (const float*)d_in[8];
    const float* bv = (const float*)d_in[9];
    float* out = (float*)d_out;

    static cudaStream_t s2 = nullptr;
    static cudaEvent_t ev_start = nullptr, ev_wt = nullptr,
                       ev_fork = nullptr, ev_join = nullptr;
    if (!s2) {
        cudaFuncSetAttribute(qkv_mma_kernel,
                             cudaFuncAttributeMaxDynamicSharedMemorySize, SM_BYTES);
        cudaFuncSetAttribute(scores_mma_kernel,
                             cudaFuncAttributeMaxDynamicSharedMemorySize, SM_BYTES);
        cudaFuncSetAttribute(av_mma_kernel,
                             cudaFuncAttributeMaxDynamicSharedMemorySize, SM_BYTES);
        cudaStreamCreateWithFlags(&s2, cudaStreamNonBlocking);
        cudaEventCreateWithFlags(&ev_start, cudaEventDisableTiming);
        cudaEventCreateWithFlags(&ev_wt, cudaEventDisableTiming);
        cudaEventCreateWithFlags(&ev_fork, cudaEventDisableTiming);
        cudaEventCreateWithFlags(&ev_join, cudaEventDisableTiming);
    }

    const int cvt_blocks = NROWS * D_ / (256 * 4);

    // Root s2 off the origin stream (required under capture).
    cudaEventRecord(ev_start, 0);
    cudaStreamWaitEvent(s2, ev_start, 0);

    // s2: weight transpose, then v convert (both off critical path).
    wt_kernel<<<dim3(32, 32, 3), dim3(256), 0, s2>>>(Wq, Wk, Wv);
    cudaEventRecord(ev_wt, s2);
    cvt_inputs_kernel<<<dim3(cvt_blocks, 1, 1), dim3(256), 0, s2>>>(
        query, key, value, 2);

    // main: q,k converts, then q,k projections (after wt).
    cvt_inputs_kernel<<<dim3(cvt_blocks, 1, 2), dim3(256)>>>(query, key, value, 0);
    cudaStreamWaitEvent(0, ev_wt, 0);
    qkv_mma_kernel<<<dim3(D_ / 128, NROWS / 128, 2), dim3(NTHR), SM_BYTES>>>(
        bq, bk, bv, 0);

    // Fork: v projection on s2 (after its cvt, same stream), overlapping scores.
    cudaEventRecord(ev_fork, 0);
    cudaStreamWaitEvent(s2, ev_fork, 0);
    qkv_mma_kernel<<<dim3(D_ / 128, NROWS / 128, 1), dim3(NTHR), SM_BYTES, s2>>>(
        bq, bk, bv, 2);

    // main: scores + softmax (concurrent with v projection).
    scores_mma_kernel<<<dim3(NTRI, B_), dim3(NTHR), SM_BYTES>>>();
    softmax_kernel<<<dim3(S_, B_), dim3(256)>>>();

    // Join: av needs both P (main) and V^T (s2).
    cudaEventRecord(ev_join, s2);
    cudaStreamWaitEvent(0, ev_join, 0);

    av_mma_kernel<<<dim3(D_ / 128, S_ / 128, B_), dim3(NTHR), SM_BYTES>>>(out);
}